// round 4
// baseline (speedup 1.0000x reference)
#include <cuda_runtime.h>

#define HH   256
#define WWD  256
#define PIX  (HH * WWD)
#define NCH  29
#define NB   2
#define NTAP 49

// Persistent scratch (allocation-free rule: __device__ globals).
__device__ __align__(128) float g_W[NB * NTAP * PIX];      // combined per-pixel 7x7 weights
__device__ __align__(128) float g_q[2][NB * NCH * PIX];    // ping-pong q buffers

// ---------------------------------------------------------------------------
// Kernel 1: W[k,p] = sw[k] * (3 + 10*exp(-||I(p+k)-I(p)||^2 / 200)), 0 if OOB
// ---------------------------------------------------------------------------
__global__ void compute_w_kernel(const float* __restrict__ img) {
    int p = blockIdx.x * blockDim.x + threadIdx.x;
    int b = blockIdx.y;
    int y = p >> 8, x = p & 255;
    const float* im = img + (size_t)b * 3 * PIX;
    float r0 = im[p], gg0 = im[PIX + p], bb0 = im[2 * PIX + p];

    // normalized 1D gaussian (sigma=3, size 7)
    float g1[7]; float s = 0.f;
    #pragma unroll
    for (int i = 0; i < 7; i++) {
        float d = (float)i - 3.0f;
        g1[i] = __expf(-d * d * (1.0f / 18.0f));
        s += g1[i];
    }
    float inv = __fdividef(1.0f, s);
    #pragma unroll
    for (int i = 0; i < 7; i++) g1[i] *= inv;

    float* wp = g_W + (size_t)b * NTAP * PIX;
    #pragma unroll
    for (int dy = 0; dy < 7; dy++) {
        int ny = y + dy - 3;
        #pragma unroll
        for (int dx = 0; dx < 7; dx++) {
            int nx = x + dx - 3;
            float wv = 0.f;
            if (ny >= 0 && ny < HH && nx >= 0 && nx < WWD) {
                int np = ny * WWD + nx;
                float dr = im[np] - r0;
                float dg = im[PIX + np] - gg0;
                float db = im[2 * PIX + np] - bb0;
                float d2 = dr * dr + dg * dg + db * db;
                wv = g1[dy] * g1[dx] * (3.0f + 10.0f * __expf(-d2 * 0.005f));
            }
            wp[(dy * 7 + dx) * PIX + p] = wv;
        }
    }
}

// ---------------------------------------------------------------------------
// Kernel 2: q0 = softmax(-unary) over channel axis. One thread = 4 pixels.
// ---------------------------------------------------------------------------
__global__ void init_q_kernel(const float* __restrict__ unary) {
    int i = blockIdx.x * blockDim.x + threadIdx.x;  // float4 index
    int b = blockIdx.y;
    const float* ub = unary + (size_t)b * NCH * PIX;
    float*       qb = g_q[0] + (size_t)b * NCH * PIX;

    float4 l[NCH];
    float4 m = make_float4(-1e30f, -1e30f, -1e30f, -1e30f);
    #pragma unroll
    for (int c = 0; c < NCH; c++) {
        float4 u = __ldg((const float4*)(ub + c * PIX) + i);
        l[c] = make_float4(-u.x, -u.y, -u.z, -u.w);
        m.x = fmaxf(m.x, l[c].x); m.y = fmaxf(m.y, l[c].y);
        m.z = fmaxf(m.z, l[c].z); m.w = fmaxf(m.w, l[c].w);
    }
    float4 s = make_float4(0.f, 0.f, 0.f, 0.f);
    #pragma unroll
    for (int c = 0; c < NCH; c++) {
        l[c].x = __expf(l[c].x - m.x); s.x += l[c].x;
        l[c].y = __expf(l[c].y - m.y); s.y += l[c].y;
        l[c].z = __expf(l[c].z - m.z); s.z += l[c].z;
        l[c].w = __expf(l[c].w - m.w); s.w += l[c].w;
    }
    float4 r = make_float4(__fdividef(1.f, s.x), __fdividef(1.f, s.y),
                           __fdividef(1.f, s.z), __fdividef(1.f, s.w));
    #pragma unroll
    for (int c = 0; c < NCH; c++) {
        float4 o = make_float4(l[c].x * r.x, l[c].y * r.y, l[c].z * r.z, l[c].w * r.w);
        *((float4*)(qb + c * PIX) + i) = o;
    }
}

// ---------------------------------------------------------------------------
// Kernel 3: one mean-field iteration: q_out = softmax(-unary + W (*) q_in)
// CTA tile = 64x8 pixels, 128 threads (16x8), 4 horizontal px per thread.
// Channels processed in smem chunks of 8 (tile+halo = 14 rows x 72-stride).
// ---------------------------------------------------------------------------
#define SPLANE 1008   // 14 * 72
#define SSTR   72

template<int C0, int NC>
__device__ __forceinline__ void conv_chunk(
    const float* __restrict__ qin_b,
    float* __restrict__ qs,
    float (&z)[NCH][4],
    const int (&goffs)[8], unsigned lmask, unsigned smask,
    int tid, int px, int py,
    const float* __restrict__ wbase)
{
    // cooperative fill of NC channel tiles (with zero halo)
    #pragma unroll
    for (int cc = 0; cc < NC; cc++) {
        const float* src = qin_b + (C0 + cc) * PIX;
        #pragma unroll
        for (int j = 0; j < 8; j++) {
            if (smask & (1u << j)) {
                float v = (lmask & (1u << j)) ? __ldg(src + goffs[j]) : 0.f;
                qs[cc * SPLANE + tid + j * 128] = v;
            }
        }
    }
    __syncthreads();

    #pragma unroll 1
    for (int dy = 0; dy < 7; dy++) {
        float4 w4[7];
        const float* wrow = wbase + dy * 7 * PIX;
        #pragma unroll
        for (int dx = 0; dx < 7; dx++)
            w4[dx] = __ldg((const float4*)(wrow + dx * PIX));
        #pragma unroll
        for (int cc = 0; cc < NC; cc++) {
            const float* qr = qs + cc * SPLANE + (py + dy) * SSTR + px;
            float4 qa = *(const float4*)qr;
            float4 qb = *(const float4*)(qr + 4);
            float2 qc = *(const float2*)(qr + 8);
            float qv[10] = {qa.x, qa.y, qa.z, qa.w, qb.x, qb.y, qb.z, qb.w, qc.x, qc.y};
            #pragma unroll
            for (int dx = 0; dx < 7; dx++) {
                z[C0 + cc][0] = fmaf(w4[dx].x, qv[dx + 0], z[C0 + cc][0]);
                z[C0 + cc][1] = fmaf(w4[dx].y, qv[dx + 1], z[C0 + cc][1]);
                z[C0 + cc][2] = fmaf(w4[dx].z, qv[dx + 2], z[C0 + cc][2]);
                z[C0 + cc][3] = fmaf(w4[dx].w, qv[dx + 3], z[C0 + cc][3]);
            }
        }
    }
    __syncthreads();
}

__global__ __launch_bounds__(128, 2) void crf_iter_kernel(
    const float* __restrict__ unary, int src, float* __restrict__ qout_last)
{
    __shared__ float qs[8 * SPLANE];   // 31.5 KB
    int tx = threadIdx.x, ty = threadIdx.y;
    int tid = ty * 16 + tx;
    int x0 = blockIdx.x * 64, y0 = blockIdx.y * 8;
    int b = blockIdx.z;

    const float* qin_b = g_q[src] + (size_t)b * NCH * PIX;
    float* qout = qout_last ? qout_last : g_q[src ^ 1];
    float* qout_b = qout + (size_t)b * NCH * PIX;
    const float* wbase = g_W + (size_t)b * NTAP * PIX + (y0 + ty) * WWD + x0 + tx * 4;

    // precompute halo-fill addressing: 1008 smem slots / 128 threads -> 8 each
    int goffs[8]; unsigned lmask = 0, smask = 0;
    #pragma unroll
    for (int j = 0; j < 8; j++) {
        int idx = tid + j * 128;
        int row = idx / SSTR;
        int col = idx - row * SSTR;
        int gy = y0 - 3 + row, gx = x0 - 3 + col;
        bool instore = idx < SPLANE;
        bool v = instore && (col < 70) && gy >= 0 && gy < HH && gx >= 0 && gx < WWD;
        goffs[j] = v ? gy * WWD + gx : 0;
        if (instore) smask |= 1u << j;
        if (v)       lmask |= 1u << j;
    }

    float z[NCH][4];
    #pragma unroll
    for (int c = 0; c < NCH; c++) { z[c][0] = 0.f; z[c][1] = 0.f; z[c][2] = 0.f; z[c][3] = 0.f; }

    int px = tx * 4, py = ty;
    conv_chunk< 0, 8>(qin_b, qs, z, goffs, lmask, smask, tid, px, py, wbase);
    conv_chunk< 8, 8>(qin_b, qs, z, goffs, lmask, smask, tid, px, py, wbase);
    conv_chunk<16, 8>(qin_b, qs, z, goffs, lmask, smask, tid, px, py, wbase);
    conv_chunk<24, 5>(qin_b, qs, z, goffs, lmask, smask, tid, px, py, wbase);

    // softmax over channels: logit = pairwise - unary
    int gp = (y0 + py) * WWD + x0 + px;
    const float* ub = unary + (size_t)b * NCH * PIX + gp;
    float4 m4 = make_float4(-1e30f, -1e30f, -1e30f, -1e30f);
    #pragma unroll
    for (int c = 0; c < NCH; c++) {
        float4 u = __ldg((const float4*)(ub + c * PIX));
        z[c][0] -= u.x; z[c][1] -= u.y; z[c][2] -= u.z; z[c][3] -= u.w;
        m4.x = fmaxf(m4.x, z[c][0]); m4.y = fmaxf(m4.y, z[c][1]);
        m4.z = fmaxf(m4.z, z[c][2]); m4.w = fmaxf(m4.w, z[c][3]);
    }
    float4 s4 = make_float4(0.f, 0.f, 0.f, 0.f);
    #pragma unroll
    for (int c = 0; c < NCH; c++) {
        z[c][0] = __expf(z[c][0] - m4.x); s4.x += z[c][0];
        z[c][1] = __expf(z[c][1] - m4.y); s4.y += z[c][1];
        z[c][2] = __expf(z[c][2] - m4.z); s4.z += z[c][2];
        z[c][3] = __expf(z[c][3] - m4.w); s4.w += z[c][3];
    }
    float4 r4 = make_float4(__fdividef(1.f, s4.x), __fdividef(1.f, s4.y),
                            __fdividef(1.f, s4.z), __fdividef(1.f, s4.w));
    float* ob = qout_b + gp;
    #pragma unroll
    for (int c = 0; c < NCH; c++) {
        float4 o = make_float4(z[c][0] * r4.x, z[c][1] * r4.y,
                               z[c][2] * r4.z, z[c][3] * r4.w);
        *((float4*)(ob + c * PIX)) = o;
    }
}

// ---------------------------------------------------------------------------
extern "C" void kernel_launch(void* const* d_in, const int* in_sizes, int n_in,
                              void* d_out, int out_size) {
    (void)in_sizes; (void)n_in; (void)out_size;
    const float* unary = (const float*)d_in[0];
    const float* img   = (const float*)d_in[1];
    float* out = (float*)d_out;

    compute_w_kernel<<<dim3(PIX / 256, NB), 256>>>(img);
    init_q_kernel<<<dim3(PIX / 4 / 256, NB), 256>>>(unary);

    dim3 grid(WWD / 64, HH / 8, NB), blk(16, 8);
    for (int it = 0; it < 5; it++) {
        crf_iter_kernel<<<grid, blk>>>(unary, it & 1, (it == 4) ? out : nullptr);
    }
}

// round 7
// speedup vs baseline: 1.3650x; 1.3650x over previous
#include <cuda_runtime.h>

#define HH   256
#define WWD  256
#define PIX  (HH * WWD)
#define NCH  29
#define NB   2
#define NTAP 49
#define SPLANE 1008   // 14 * 72
#define SSTR   72

// Persistent scratch (allocation-free rule: __device__ globals).
__device__ __align__(128) float g_W[NB * NTAP * PIX];   // combined per-pixel 7x7 weights
__device__ __align__(128) float g_q[NB * NCH * PIX];    // current q (in-place update)
__device__ __align__(128) float g_P[NB * NCH * PIX];    // pairwise scratch

// ---------------------------------------------------------------------------
// Kernel 1: W[k,p] = sw[k] * (3 + 10*exp(-||I(p+k)-I(p)||^2 / 200)), 0 if OOB
// ---------------------------------------------------------------------------
__global__ void compute_w_kernel(const float* __restrict__ img) {
    int p = blockIdx.x * blockDim.x + threadIdx.x;
    int b = blockIdx.y;
    int y = p >> 8, x = p & 255;
    const float* im = img + (size_t)b * 3 * PIX;
    float r0 = im[p], gg0 = im[PIX + p], bb0 = im[2 * PIX + p];

    // normalized 1D gaussian (sigma=3, size 7)
    float g1[7]; float s = 0.f;
    #pragma unroll
    for (int i = 0; i < 7; i++) {
        float d = (float)i - 3.0f;
        g1[i] = __expf(-d * d * (1.0f / 18.0f));
        s += g1[i];
    }
    float inv = __fdividef(1.0f, s);
    #pragma unroll
    for (int i = 0; i < 7; i++) g1[i] *= inv;

    float* wp = g_W + (size_t)b * NTAP * PIX;
    #pragma unroll
    for (int dy = 0; dy < 7; dy++) {
        int ny = y + dy - 3;
        #pragma unroll
        for (int dx = 0; dx < 7; dx++) {
            int nx = x + dx - 3;
            float wv = 0.f;
            if (ny >= 0 && ny < HH && nx >= 0 && nx < WWD) {
                int np = ny * WWD + nx;
                float dr = im[np] - r0;
                float dg = im[PIX + np] - gg0;
                float db = im[2 * PIX + np] - bb0;
                float d2 = dr * dr + dg * dg + db * db;
                wv = g1[dy] * g1[dx] * (3.0f + 10.0f * __expf(-d2 * 0.005f));
            }
            wp[(dy * 7 + dx) * PIX + p] = wv;
        }
    }
}

// ---------------------------------------------------------------------------
// Kernel 2: softmax over channels. use_p=0: logits=-unary (init).
//           use_p=1: logits=P-unary (mean-field update). Writes qdst (or g_q).
// ---------------------------------------------------------------------------
__global__ __launch_bounds__(256) void softmax_kernel(
    const float* __restrict__ unary, int use_p, float* __restrict__ qdst)
{
    int i = blockIdx.x * blockDim.x + threadIdx.x;  // float4 pixel index
    int b = blockIdx.y;
    const float4* ub = (const float4*)(unary + (size_t)b * NCH * PIX);
    const float4* pb = (const float4*)(g_P + (size_t)b * NCH * PIX);
    float4* qb = (float4*)((qdst ? qdst : g_q) + (size_t)b * NCH * PIX);
    const int s4 = PIX / 4;

    float4 l[NCH];
    float4 m = make_float4(-1e30f, -1e30f, -1e30f, -1e30f);
    #pragma unroll
    for (int c = 0; c < NCH; c++) {
        float4 u = __ldg(ub + c * s4 + i);
        if (use_p) {
            float4 p = __ldg(pb + c * s4 + i);
            l[c] = make_float4(p.x - u.x, p.y - u.y, p.z - u.z, p.w - u.w);
        } else {
            l[c] = make_float4(-u.x, -u.y, -u.z, -u.w);
        }
        m.x = fmaxf(m.x, l[c].x); m.y = fmaxf(m.y, l[c].y);
        m.z = fmaxf(m.z, l[c].z); m.w = fmaxf(m.w, l[c].w);
    }
    float4 s = make_float4(0.f, 0.f, 0.f, 0.f);
    #pragma unroll
    for (int c = 0; c < NCH; c++) {
        l[c].x = __expf(l[c].x - m.x); s.x += l[c].x;
        l[c].y = __expf(l[c].y - m.y); s.y += l[c].y;
        l[c].z = __expf(l[c].z - m.z); s.z += l[c].z;
        l[c].w = __expf(l[c].w - m.w); s.w += l[c].w;
    }
    float4 r = make_float4(__fdividef(1.f, s.x), __fdividef(1.f, s.y),
                           __fdividef(1.f, s.z), __fdividef(1.f, s.w));
    #pragma unroll
    for (int c = 0; c < NCH; c++) {
        qb[c * s4 + i] = make_float4(l[c].x * r.x, l[c].y * r.y,
                                     l[c].z * r.z, l[c].w * r.w);
    }
}

// ---------------------------------------------------------------------------
// Kernel 3: pairwise conv: P[c,p] = sum_k W[k,p]*q[c,p+k]
// CTA = 64x8 spatial tile x 8-channel group. 128 threads, 4 px/thread.
// ---------------------------------------------------------------------------
template<int NC>
__device__ __forceinline__ void conv_group(
    const float* __restrict__ qin_b, float* __restrict__ Pb, int c0,
    float* __restrict__ qs,
    const int (&goffs)[8], unsigned lmask, unsigned smask,
    int tid, int px, int py, const float* __restrict__ wbase, int gp)
{
    // cooperative fill of NC channel tiles (with zero halo)
    #pragma unroll
    for (int cc = 0; cc < NC; cc++) {
        const float* src = qin_b + (c0 + cc) * PIX;
        #pragma unroll
        for (int j = 0; j < 8; j++) {
            if (smask & (1u << j)) {
                float v = (lmask & (1u << j)) ? __ldg(src + goffs[j]) : 0.f;
                qs[cc * SPLANE + tid + j * 128] = v;
            }
        }
    }
    __syncthreads();

    float z[NC][4];
    #pragma unroll
    for (int cc = 0; cc < NC; cc++) { z[cc][0] = 0.f; z[cc][1] = 0.f; z[cc][2] = 0.f; z[cc][3] = 0.f; }

    #pragma unroll 1
    for (int dy = 0; dy < 7; dy++) {
        float4 w4[7];
        const float* wrow = wbase + dy * 7 * PIX;
        #pragma unroll
        for (int dx = 0; dx < 7; dx++)
            w4[dx] = __ldg((const float4*)(wrow + dx * PIX));
        #pragma unroll
        for (int cc = 0; cc < NC; cc++) {
            const float* qr = qs + cc * SPLANE + (py + dy) * SSTR + px;
            float4 qa = *(const float4*)qr;
            float4 qb4 = *(const float4*)(qr + 4);
            float2 qc = *(const float2*)(qr + 8);
            float qv[10] = {qa.x, qa.y, qa.z, qa.w, qb4.x, qb4.y, qb4.z, qb4.w, qc.x, qc.y};
            #pragma unroll
            for (int dx = 0; dx < 7; dx++) {
                z[cc][0] = fmaf(w4[dx].x, qv[dx + 0], z[cc][0]);
                z[cc][1] = fmaf(w4[dx].y, qv[dx + 1], z[cc][1]);
                z[cc][2] = fmaf(w4[dx].z, qv[dx + 2], z[cc][2]);
                z[cc][3] = fmaf(w4[dx].w, qv[dx + 3], z[cc][3]);
            }
        }
    }

    #pragma unroll
    for (int cc = 0; cc < NC; cc++)
        *(float4*)(Pb + (size_t)(c0 + cc) * PIX + gp) =
            make_float4(z[cc][0], z[cc][1], z[cc][2], z[cc][3]);
}

__global__ __launch_bounds__(128, 4) void pairwise_kernel() {
    __shared__ float qs[8 * SPLANE];   // 31.5 KB
    int tx = threadIdx.x, ty = threadIdx.y;        // 16 x 8
    int tid = ty * 16 + tx;
    int x0 = blockIdx.x * 64, y0 = blockIdx.y * 8;
    int zb = blockIdx.z;                            // 0..4*NB-1
    int b = zb >> 2, grp = zb & 3;

    const float* qin_b = g_q + (size_t)b * NCH * PIX;
    float* Pb = g_P + (size_t)b * NCH * PIX;
    const float* wbase = g_W + (size_t)b * NTAP * PIX + (y0 + ty) * WWD + x0 + tx * 4;

    // halo-fill addressing: 1008 smem slots / 128 threads -> 8 each
    int goffs[8]; unsigned lmask = 0, smask = 0;
    #pragma unroll
    for (int j = 0; j < 8; j++) {
        int idx = tid + j * 128;
        int row = idx / SSTR;
        int col = idx - row * SSTR;
        int gy = y0 - 3 + row, gx = x0 - 3 + col;
        bool instore = idx < SPLANE;
        bool v = instore && (col < 70) && gy >= 0 && gy < HH && gx >= 0 && gx < WWD;
        goffs[j] = v ? gy * WWD + gx : 0;
        if (instore) smask |= 1u << j;
        if (v)       lmask |= 1u << j;
    }

    int px = tx * 4, py = ty;
    int gp = (y0 + py) * WWD + x0 + px;

    if (grp < 3)
        conv_group<8>(qin_b, Pb, grp * 8, qs, goffs, lmask, smask, tid, px, py, wbase, gp);
    else
        conv_group<5>(qin_b, Pb, 24, qs, goffs, lmask, smask, tid, px, py, wbase, gp);
}

// ---------------------------------------------------------------------------
extern "C" void kernel_launch(void* const* d_in, const int* in_sizes, int n_in,
                              void* d_out, int out_size) {
    (void)in_sizes; (void)n_in; (void)out_size;
    const float* unary = (const float*)d_in[0];
    const float* img   = (const float*)d_in[1];
    float* out = (float*)d_out;

    compute_w_kernel<<<dim3(PIX / 256, NB), 256>>>(img);
    softmax_kernel<<<dim3(PIX / 4 / 256, NB), 256>>>(unary, 0, nullptr);   // init q

    dim3 pgrid(WWD / 64, HH / 8, 4 * NB), pblk(16, 8);
    for (int it = 0; it < 5; it++) {
        pairwise_kernel<<<pgrid, pblk>>>();
        softmax_kernel<<<dim3(PIX / 4 / 256, NB), 256>>>(unary, 1, (it == 4) ? out : nullptr);
    }
}